// round 1
// baseline (speedup 1.0000x reference)
#include <cuda_runtime.h>
#include <math.h>

#define BSZ 4
#define HH 480
#define WW 640
#define CC 20
#define MSZ 480
#define VRD 100
#define NZD 48
#define NFEAT 17          // 1 occupancy + 16 semantic
#define AVC 19            // 0:fp_map 1:fp_exp 2..17:sem 18:fp_stair
#define NPIX (MSZ*MSZ)    // 230400
#define VOX_PER_CH (VRD*VRD*NZD)   // 480000
#define VOX_TOTAL (BSZ*NFEAT*VOX_PER_CH)

// ---------------- device scratch (static, no allocation) ----------------
__device__ float g_vox[VOX_TOTAL];                 // ~130.6 MB
__device__ float g_av [BSZ*AVC*VRD*VRD];           // compact agent view
__device__ float g_rot[BSZ*AVC*NPIX];              // rotated 480x480, 19 ch
__device__ float g_ts0[BSZ*NPIX];                  // translated_stair ch0
__device__ float g_par[BSZ][6];                    // ct, st, sx, sy, ca, sa
__device__ float g_F;                              // focal constant
__device__ int   g_sc[2];                          // stair center (s_x, s_y)

// ---------------- K1: pose + params ----------------
__global__ void k_pose(const float* __restrict__ pose_obs,
                       const float* __restrict__ poses_last,
                       const float* __restrict__ eve_angle,
                       float* __restrict__ out_poses)
{
    int b = threadIdx.x;
    if (b >= BSZ) return;
    const float R2D = 57.29577951308232f;
    float px = poses_last[b*3+0];
    float py = poses_last[b*3+1];
    float pt = poses_last[b*3+2];
    float r = pt / R2D;
    float sr, cr; sincosf(r, &sr, &cr);
    float ox = pose_obs[b*3+0], oy = pose_obs[b*3+1], ot = pose_obs[b*3+2];
    float ny = py + ox*sr + oy*cr;
    float nx = px + ox*cr - oy*sr;
    float nt = pt + ot*R2D;
    nt = fmodf(nt - 180.0f, 360.0f) + 180.0f;
    nt = fmodf(nt + 180.0f, 360.0f) - 180.0f;
    out_poses[b*3+0] = nx;
    out_poses[b*3+1] = ny;
    out_poses[b*3+2] = nt;

    const float half = 240.0f;
    float sx = (half - nx*100.0f/5.0f)/half;
    float sy = (half - ny*100.0f/5.0f)/half;
    float t = (90.0f - nt) * (float)(M_PI/180.0);
    float st, ct; sincosf(t, &st, &ct);
    float a = eve_angle[b] * (float)(M_PI/180.0);
    float sa, ca; sincosf(a, &sa, &ca);
    g_par[b][0] = ct; g_par[b][1] = st;
    g_par[b][2] = sx; g_par[b][3] = sy;
    g_par[b][4] = ca; g_par[b][5] = sa;
    if (b == 0) {
        g_F = (float)(320.0 / tan(39.5 * M_PI / 180.0));
        int sxi = (int)(nx * 100.0f / 5.0f);   // trunc toward zero, matches astype(int32)
        int syi = (int)(ny * 100.0f / 5.0f);
        sxi = min(max(sxi, 30), MSZ - 30 - 1);
        syi = min(max(syi, 30), MSZ - 30 - 1);
        g_sc[0] = sxi; g_sc[1] = syi;
    }
}

// ---------------- K2: zero voxel scratch ----------------
__global__ void k_zero()
{
    size_t i = (size_t)blockIdx.x*blockDim.x + threadIdx.x;
    size_t n = VOX_TOTAL/4;
    if (i < n) reinterpret_cast<float4*>(g_vox)[i] = make_float4(0.f,0.f,0.f,0.f);
}

// ---------------- K3: trilinear splat (atomics) ----------------
__global__ void __launch_bounds__(256) k_splat(const float* __restrict__ obs)
{
    int idx = blockIdx.x*blockDim.x + threadIdx.x;
    if (idx >= BSZ*HH*WW) return;
    int b   = idx / (HH*WW);
    int pix = idx - b*(HH*WW);
    int i   = pix / WW;
    int j   = pix - i*WW;

    float F  = g_F;
    float ca = g_par[b][4], sa = g_par[b][5];
    const float* ob = obs + (size_t)b*CC*HH*WW;
    float d  = ob[(3*HH + i)*WW + j];

    float X  = ((float)j - 319.5f) * d / F + 250.0f;
    float Zc = ((float)(HH-1-i) - 239.5f) * d / F;
    float Y  = ca*d - sa*Zc;
    float Z  = sa*d + ca*Zc + 88.0f;

    float xs = ((X/5.0f - 50.0f)/100.0f)*2.0f;
    float ys = ((Y/5.0f - 50.0f)/100.0f)*2.0f;
    float zs = ((Z/5.0f - 16.0f)/48.0f)*2.0f;
    float p0 = xs*50.0f + 50.0f;
    float p1 = ys*50.0f + 50.0f;
    float p2 = zs*24.0f + 24.0f;

    float f0 = floorf(p0), f1 = floorf(p1), f2 = floorf(p2);
    // both corners invalid -> nothing to do (validity is pix>0 && pix<D, strict)
    if (f0 <= -1.0f || f0 >= 100.0f) return;
    if (f1 <= -1.0f || f1 >= 100.0f) return;
    if (f2 <= -1.0f || f2 >= 48.0f)  return;

    // semantic channels are only consumed via z in [13,35)
    bool need_sem = false;
    #pragma unroll
    for (int iz = 0; iz < 2; ++iz) {
        float zf = f2 + (float)iz;
        if (zf >= 13.0f && zf < 35.0f && zf > 0.0f && zf < 48.0f) need_sem = true;
    }
    float sem[16];
    if (need_sem) {
        #pragma unroll
        for (int c = 0; c < 16; ++c)
            sem[c] = ob[((4+c)*HH + i)*WW + j];
    }

    float* voxb = g_vox + (size_t)b*NFEAT*VOX_PER_CH;
    #pragma unroll
    for (int ix = 0; ix < 2; ++ix) {
        float xf = f0 + (float)ix;
        if (!(xf > 0.0f && xf < 100.0f)) continue;
        float wx = 1.0f - fabsf(p0 - xf);
        int xi = (int)xf;
        #pragma unroll
        for (int iy = 0; iy < 2; ++iy) {
            float yf = f1 + (float)iy;
            if (!(yf > 0.0f && yf < 100.0f)) continue;
            float wxy = wx * (1.0f - fabsf(p1 - yf));
            int yi = (int)yf;
            int bxy = (xi*VRD + yi)*NZD;
            #pragma unroll
            for (int iz = 0; iz < 2; ++iz) {
                float zf = f2 + (float)iz;
                if (!(zf > 0.0f && zf < 48.0f)) continue;
                float w = wxy * (1.0f - fabsf(p2 - zf));
                if (w == 0.0f) continue;
                int zi = (int)zf;
                int off = bxy + zi;
                atomicAdd(voxb + off, w);
                if (zi >= 13 && zi < 35) {
                    #pragma unroll
                    for (int c = 0; c < 16; ++c)
                        atomicAdd(voxb + (size_t)(1+c)*VOX_PER_CH + off, w*sem[c]);
                }
            }
        }
    }
}

// ---------------- K4: round + z-range reductions -> compact agent view ----------------
__global__ void k_reduce()
{
    int idx = blockIdx.x*blockDim.x + threadIdx.x;
    if (idx >= BSZ*NFEAT*VRD*VRD) return;
    int b  = idx / (NFEAT*VRD*VRD);
    int r0 = idx - b*(NFEAT*VRD*VRD);
    int f  = r0 / (VRD*VRD);
    int r1 = r0 - f*(VRD*VRD);
    int yi = r1 / VRD;
    int xi = r1 - yi*VRD;
    // voxels[b,f,x,y,z] flat; output indexed [y,x] (transpose in ref)
    const float* v = g_vox + ((size_t)(b*NFEAT+f)*VRD*VRD + (size_t)xi*VRD + yi)*NZD;
    int avbase = (b*AVC)*(VRD*VRD) + yi*VRD + xi;
    if (f == 0) {
        float all = 0.f, ah = 0.f, as = 0.f;
        #pragma unroll
        for (int z = 0; z < 48; ++z) {
            float r = rintf(v[z]);
            all += r;
            if (z >= 13 && z < 35) ah += r;
            if (z >= 20 && z < 25) as += r;
        }
        g_av[avbase]                 = fminf(fmaxf(ah , 0.f), 1.f);  // fp_map
        g_av[avbase + VRD*VRD]       = fminf(fmaxf(all, 0.f), 1.f);  // fp_exp
        g_av[avbase + 18*VRD*VRD]    = fminf(fmaxf(as , 0.f), 1.f);  // fp_stair
    } else {
        float ah = 0.f;
        #pragma unroll
        for (int z = 13; z < 35; ++z) ah += rintf(v[z]);
        g_av[avbase + (1+f)*VRD*VRD] = fminf(fmaxf(ah/5.0f, 0.f), 1.f);
    }
}

// ---------------- K5: rotation grid_sample ----------------
__device__ __forceinline__ float av_fetch(int b, int ch, int ix, int iy)
{
    if (iy < 240 || iy >= 340 || ix < 190 || ix >= 290) return 0.f;
    return g_av[(b*AVC + ch)*(VRD*VRD) + (iy-240)*VRD + (ix-190)];
}

__global__ void __launch_bounds__(256) k_rot()
{
    int idx = blockIdx.x*blockDim.x + threadIdx.x;
    if (idx >= BSZ*NPIX) return;
    int b = idx / NPIX;
    int p = idx - b*NPIX;
    int h = p / MSZ, w = p - h*MSZ;
    float ct = g_par[b][0], st = g_par[b][1];
    float gx = ((float)w + 0.5f)*2.0f/480.0f - 1.0f;
    float gy = ((float)h + 0.5f)*2.0f/480.0f - 1.0f;
    float u = ct*gx - st*gy;
    float v = st*gx + ct*gy;
    float x = (u + 1.0f)*0.5f*479.0f;
    float y = (v + 1.0f)*0.5f*479.0f;
    float x0f = floorf(x), y0f = floorf(y);
    int x0 = (int)x0f, y0 = (int)y0f;
    float wx = x - x0f, wy = y - y0f;
    float* out = g_rot + (size_t)b*AVC*NPIX + p;
    if (x0+1 < 190 || x0 > 289 || y0+1 < 240 || y0 > 339) {
        #pragma unroll
        for (int ch = 0; ch < AVC; ++ch) out[(size_t)ch*NPIX] = 0.f;
        return;
    }
    float w00 = (1.f-wx)*(1.f-wy), w10 = wx*(1.f-wy);
    float w01 = (1.f-wx)*wy,       w11 = wx*wy;
    #pragma unroll
    for (int ch = 0; ch < AVC; ++ch) {
        float val = w00*av_fetch(b,ch,x0,  y0  )
                  + w10*av_fetch(b,ch,x0+1,y0  )
                  + w01*av_fetch(b,ch,x0,  y0+1)
                  + w11*av_fetch(b,ch,x0+1,y0+1);
        out[(size_t)ch*NPIX] = val;
    }
}

// ---------------- K6: translation grid_sample -> translated (output 0) ----------------
__global__ void __launch_bounds__(256) k_trans(float* __restrict__ translated)
{
    int idx = blockIdx.x*blockDim.x + threadIdx.x;
    if (idx >= BSZ*NPIX) return;
    int b = idx / NPIX;
    int p = idx - b*NPIX;
    int h = p / MSZ, w = p - h*MSZ;
    float sx = g_par[b][2], sy = g_par[b][3];
    float gx = ((float)w + 0.5f)*2.0f/480.0f - 1.0f;
    float gy = ((float)h + 0.5f)*2.0f/480.0f - 1.0f;
    float x = (gx + sx + 1.0f)*0.5f*479.0f;
    float y = (gy + sy + 1.0f)*0.5f*479.0f;
    float x0f = floorf(x), y0f = floorf(y);
    int x0 = (int)x0f, y0 = (int)y0f;
    float wx = x - x0f, wy = y - y0f;

    float* to = translated + (size_t)b*CC*NPIX + p;
    float res[AVC];
    bool any = !(x0+1 < 0 || x0 > 479 || y0+1 < 0 || y0 > 479);
    if (!any) {
        #pragma unroll
        for (int ch = 0; ch < AVC; ++ch) res[ch] = 0.f;
    } else {
        bool vx0 = (x0   >= 0 && x0   < 480);
        bool vx1 = (x0+1 >= 0 && x0+1 < 480);
        bool vy0 = (y0   >= 0 && y0   < 480);
        bool vy1 = (y0+1 >= 0 && y0+1 < 480);
        float w00 = (1.f-wx)*(1.f-wy), w10 = wx*(1.f-wy);
        float w01 = (1.f-wx)*wy,       w11 = wx*wy;
        const float* rb = g_rot + (size_t)b*AVC*NPIX;
        #pragma unroll
        for (int ch = 0; ch < AVC; ++ch) {
            const float* rc = rb + (size_t)ch*NPIX;
            float v00 = (vx0 && vy0) ? rc[y0*MSZ + x0]         : 0.f;
            float v10 = (vx1 && vy0) ? rc[y0*MSZ + x0 + 1]     : 0.f;
            float v01 = (vx0 && vy1) ? rc[(y0+1)*MSZ + x0]     : 0.f;
            float v11 = (vx1 && vy1) ? rc[(y0+1)*MSZ + x0 + 1] : 0.f;
            res[ch] = w00*v00 + w10*v10 + w01*v01 + w11*v11;
        }
    }
    to[0]            = res[0];
    to[(size_t)NPIX] = res[1];
    to[(size_t)2*NPIX] = 0.f;
    to[(size_t)3*NPIX] = 0.f;
    #pragma unroll
    for (int k = 0; k < 16; ++k)
        to[(size_t)(4+k)*NPIX] = res[2+k];
    g_ts0[(size_t)b*NPIX + p] = res[18];
}

// ---------------- K7: maxpool + kill + map fusion ----------------
__global__ void __launch_bounds__(256) k_final(const float* __restrict__ maps_last,
                                               const float* __restrict__ eve_angle,
                                               const float* __restrict__ translated,
                                               float* __restrict__ map_pred,
                                               float* __restrict__ map_pred_stair)
{
    int idx = blockIdx.x*blockDim.x + threadIdx.x;
    if (idx >= BSZ*NPIX) return;
    int b = idx / NPIX;
    int p = idx - b*NPIX;
    int h = p / MSZ, w = p - h*MSZ;

    const float* tb = translated + (size_t)b*CC*NPIX;
    float mp = -INFINITY;
    #pragma unroll
    for (int dy = -1; dy <= 1; ++dy) {
        int hy = h + dy;
        if (hy < 0 || hy >= MSZ) continue;
        #pragma unroll
        for (int dx = -1; dx <= 1; ++dx) {
            int wx = w + dx;
            if (wx < 0 || wx >= MSZ) continue;
            mp = fmaxf(mp, tb[hy*MSZ + wx]);
        }
    }
    float t1v = tb[(size_t)NPIX + p];
    bool eve0 = (eve_angle[b] == 0.0f);
    bool kill = ((t1v - mp) > 0.8f) && eve0;

    float ts0 = g_ts0[(size_t)b*NPIX + p];
    float ts1 = t1v;
    if (b == 0) {
        float sm = 0.f;
        int ys0 = g_sc[1] - 30, xs0 = g_sc[0] - 30;
        int ii = h - ys0, jj = w - xs0;
        if (ii >= 0 && ii < 60 && jj >= 0 && jj < 60) {
            float di = (float)ii + 0.5f - 30.0f;
            float dj = (float)jj + 0.5f - 30.0f;
            if (di*di + dj*dj <= 900.0f) sm = 1.0f;
        }
        ts0 *= sm; ts1 *= sm;
    }
    bool kill_s = ((ts1 - ts0) > 0.8f) && eve0;

    const float* ml = maps_last + (size_t)b*CC*NPIX + p;
    float* mo = map_pred       + (size_t)b*CC*NPIX + p;
    float* so = map_pred_stair + (size_t)b*CC*NPIX + p;
    #pragma unroll
    for (int c = 0; c < CC; ++c) {
        float t  = tb[(size_t)c*NPIX + p];
        float m  = ml[(size_t)c*NPIX];
        float mv = fmaxf(m, t);
        float ts = (c == 0) ? ts0 : (c == 1) ? ts1 : t;
        float sv = fmaxf(m, ts);
        if (c == 0) {
            if (kill)   mv = 0.f;
            if (kill_s) sv = 0.f;
        }
        mo[(size_t)c*NPIX] = mv;
        so[(size_t)c*NPIX] = sv;
    }
}

// ---------------- launch ----------------
extern "C" void kernel_launch(void* const* d_in, const int* in_sizes, int n_in,
                              void* d_out, int out_size)
{
    const float* obs        = (const float*)d_in[0];
    const float* pose_obs   = (const float*)d_in[1];
    const float* maps_last  = (const float*)d_in[2];
    const float* poses_last = (const float*)d_in[3];
    const float* eve_angle  = (const float*)d_in[4];
    float* out = (float*)d_out;

    float* translated     = out;
    float* map_pred       = out + (size_t)BSZ*CC*NPIX;
    float* map_pred_stair = out + 2*(size_t)BSZ*CC*NPIX;
    float* out_poses      = out + 3*(size_t)BSZ*CC*NPIX;

    k_pose<<<1, 32>>>(pose_obs, poses_last, eve_angle, out_poses);
    k_zero<<<(VOX_TOTAL/4 + 255)/256, 256>>>();
    k_splat<<<(BSZ*HH*WW + 255)/256, 256>>>(obs);
    k_reduce<<<(BSZ*NFEAT*VRD*VRD + 255)/256, 256>>>();
    k_rot<<<(BSZ*NPIX + 255)/256, 256>>>();
    k_trans<<<(BSZ*NPIX + 255)/256, 256>>>(translated);
    k_final<<<(BSZ*NPIX + 255)/256, 256>>>(maps_last, eve_angle, translated,
                                           map_pred, map_pred_stair);
}

// round 2
// speedup vs baseline: 2.0803x; 2.0803x over previous
#include <cuda_runtime.h>
#include <math.h>

#define BSZ 4
#define HH 480
#define WW 640
#define CC 20
#define MSZ 480
#define VRD 100
#define NZD 48
#define SEMZ0 13
#define SEMZ1 35
#define SEMNZ 22              // semantic z-window [13,35)
#define CELLF 400             // 48 occ + 22*16 sem floats per (b,x,y) cell
#define AVC 19                // 0:fp_map 1:fp_exp 2..17:sem 18:fp_stair
#define NPIX (MSZ*MSZ)
#define NCELL (BSZ*VRD*VRD)   // 40000
#define VOX_TOTAL (NCELL*CELLF)   // 16,000,000 floats = 64 MB

// ---------------- device scratch (static, no allocation) ----------------
__device__ float4 g_vox4[VOX_TOTAL/4];             // 64 MB, 16B-aligned
__device__ float  g_av [BSZ*AVC*VRD*VRD];          // compact agent view
__device__ float  g_rot[BSZ*AVC*NPIX];             // rotated 480x480, 19 ch
__device__ float  g_ts0[BSZ*NPIX];                 // translated_stair ch0
__device__ float  g_par[BSZ][6];                   // ct, st, sx, sy, ca, sa
__device__ float  g_F;
__device__ int    g_sc[2];                         // stair center (s_x, s_y)

__device__ __forceinline__ void red_add_v4(float* p, float a, float b, float c, float d)
{
    asm volatile("red.global.add.v4.f32 [%0], {%1, %2, %3, %4};"
                 :: "l"(p), "f"(a), "f"(b), "f"(c), "f"(d) : "memory");
}

// ---------------- K1: pose + params ----------------
__global__ void k_pose(const float* __restrict__ pose_obs,
                       const float* __restrict__ poses_last,
                       const float* __restrict__ eve_angle,
                       float* __restrict__ out_poses)
{
    int b = threadIdx.x;
    if (b >= BSZ) return;
    const float R2D = 57.29577951308232f;
    float px = poses_last[b*3+0];
    float py = poses_last[b*3+1];
    float pt = poses_last[b*3+2];
    float r = pt / R2D;
    float sr, cr; sincosf(r, &sr, &cr);
    float ox = pose_obs[b*3+0], oy = pose_obs[b*3+1], ot = pose_obs[b*3+2];
    float ny = py + ox*sr + oy*cr;
    float nx = px + ox*cr - oy*sr;
    float nt = pt + ot*R2D;
    nt = fmodf(nt - 180.0f, 360.0f) + 180.0f;
    nt = fmodf(nt + 180.0f, 360.0f) - 180.0f;
    out_poses[b*3+0] = nx;
    out_poses[b*3+1] = ny;
    out_poses[b*3+2] = nt;

    const float half = 240.0f;
    float sx = (half - nx*100.0f/5.0f)/half;
    float sy = (half - ny*100.0f/5.0f)/half;
    float t = (90.0f - nt) * (float)(M_PI/180.0);
    float st, ct; sincosf(t, &st, &ct);
    float a = eve_angle[b] * (float)(M_PI/180.0);
    float sa, ca; sincosf(a, &sa, &ca);
    g_par[b][0] = ct; g_par[b][1] = st;
    g_par[b][2] = sx; g_par[b][3] = sy;
    g_par[b][4] = ca; g_par[b][5] = sa;
    if (b == 0) {
        g_F = (float)(320.0 / tan(39.5 * M_PI / 180.0));
        int sxi = (int)(nx * 100.0f / 5.0f);
        int syi = (int)(ny * 100.0f / 5.0f);
        sxi = min(max(sxi, 30), MSZ - 30 - 1);
        syi = min(max(syi, 30), MSZ - 30 - 1);
        g_sc[0] = sxi; g_sc[1] = syi;
    }
}

// ---------------- K2: zero voxel scratch ----------------
__global__ void k_zero()
{
    size_t i = (size_t)blockIdx.x*blockDim.x + threadIdx.x;
    if (i < VOX_TOTAL/4) g_vox4[i] = make_float4(0.f,0.f,0.f,0.f);
}

// ---------------- K3: trilinear splat (vector reds) ----------------
__global__ void __launch_bounds__(256) k_splat(const float* __restrict__ obs)
{
    int idx = blockIdx.x*blockDim.x + threadIdx.x;
    if (idx >= BSZ*HH*WW) return;
    int b   = idx / (HH*WW);
    int pix = idx - b*(HH*WW);
    int i   = pix / WW;
    int j   = pix - i*WW;

    float F  = g_F;
    float ca = g_par[b][4], sa = g_par[b][5];
    const float* ob = obs + (size_t)b*CC*HH*WW;
    float d  = ob[(3*HH + i)*WW + j];

    float X  = ((float)j - 319.5f) * d / F + 250.0f;
    float Zc = ((float)(HH-1-i) - 239.5f) * d / F;
    float Y  = ca*d - sa*Zc;
    float Z  = sa*d + ca*Zc + 88.0f;

    float xs = ((X/5.0f - 50.0f)/100.0f)*2.0f;
    float ys = ((Y/5.0f - 50.0f)/100.0f)*2.0f;
    float zs = ((Z/5.0f - 16.0f)/48.0f)*2.0f;
    float p0 = xs*50.0f + 50.0f;
    float p1 = ys*50.0f + 50.0f;
    float p2 = zs*24.0f + 24.0f;

    float f0 = floorf(p0), f1 = floorf(p1), f2 = floorf(p2);
    if (f0 <= -1.0f || f0 >= 100.0f) return;
    if (f1 <= -1.0f || f1 >= 100.0f) return;
    if (f2 <= -1.0f || f2 >= 48.0f)  return;

    // semantic channels consumed only via z in [13,35)
    bool need_sem = false;
    #pragma unroll
    for (int iz = 0; iz < 2; ++iz) {
        float zf = f2 + (float)iz;
        if (zf >= 13.0f && zf < 35.0f) need_sem = true;
    }
    float sem[16];
    if (need_sem) {
        #pragma unroll
        for (int c = 0; c < 16; ++c)
            sem[c] = ob[((4+c)*HH + i)*WW + j];
    }

    float* vox = reinterpret_cast<float*>(g_vox4);
    #pragma unroll
    for (int ix = 0; ix < 2; ++ix) {
        float xf = f0 + (float)ix;
        if (!(xf > 0.0f && xf < 100.0f)) continue;
        float wx = 1.0f - fabsf(p0 - xf);
        int xi = (int)xf;
        #pragma unroll
        for (int iy = 0; iy < 2; ++iy) {
            float yf = f1 + (float)iy;
            if (!(yf > 0.0f && yf < 100.0f)) continue;
            float wxy = wx * (1.0f - fabsf(p1 - yf));
            int yi = (int)yf;
            float* cellp = vox + (size_t)((b*VRD + xi)*VRD + yi)*CELLF;
            #pragma unroll
            for (int iz = 0; iz < 2; ++iz) {
                float zf = f2 + (float)iz;
                if (!(zf > 0.0f && zf < 48.0f)) continue;
                float w = wxy * (1.0f - fabsf(p2 - zf));
                if (w == 0.0f) continue;
                int zi = (int)zf;
                atomicAdd(cellp + zi, w);
                if (zi >= SEMZ0 && zi < SEMZ1) {
                    float* sp = cellp + NZD + (zi - SEMZ0)*16;
                    red_add_v4(sp     , w*sem[0],  w*sem[1],  w*sem[2],  w*sem[3]);
                    red_add_v4(sp + 4 , w*sem[4],  w*sem[5],  w*sem[6],  w*sem[7]);
                    red_add_v4(sp + 8 , w*sem[8],  w*sem[9],  w*sem[10], w*sem[11]);
                    red_add_v4(sp + 12, w*sem[12], w*sem[13], w*sem[14], w*sem[15]);
                }
            }
        }
    }
}

// ---------------- K4: warp-per-cell reduce -> compact agent view ----------------
__global__ void __launch_bounds__(256) k_reduce()
{
    int warp = (blockIdx.x*blockDim.x + threadIdx.x) >> 5;
    int lane = threadIdx.x & 31;
    if (warp >= NCELL) return;
    int b  = warp / (VRD*VRD);
    int r  = warp - b*(VRD*VRD);
    int xi = r / VRD;
    int yi = r - xi*VRD;
    const float* v = reinterpret_cast<const float*>(g_vox4) + (size_t)warp*CELLF;

    // occupancy windows
    float o1 = rintf(v[lane]);                               // z = lane
    float o2 = (lane < 16) ? rintf(v[32 + lane]) : 0.f;      // z = 32+lane
    float all = o1 + o2;
    float ah  = ((lane >= 13) ? o1 : 0.f) + ((lane < 3) ? o2 : 0.f);
    float as  = (lane >= 20 && lane < 25) ? o1 : 0.f;

    // semantic per-channel sums: lanes 0-15 -> z 0..10, lanes 16-31 -> z 11..21
    int c = lane & 15;
    int halfw = lane >> 4;
    float s = 0.f;
    const float* sv = v + NZD + c;
    #pragma unroll
    for (int t = 0; t < 11; ++t)
        s += rintf(sv[(halfw*11 + t)*16]);
    s += __shfl_xor_sync(0xffffffffu, s, 16);

    #pragma unroll
    for (int off = 16; off; off >>= 1) {
        all += __shfl_xor_sync(0xffffffffu, all, off);
        ah  += __shfl_xor_sync(0xffffffffu, ah , off);
        as  += __shfl_xor_sync(0xffffffffu, as , off);
    }

    float* avb = g_av + (size_t)b*AVC*VRD*VRD + yi*VRD + xi;
    if (lane == 0) {
        avb[0]               = fminf(fmaxf(ah , 0.f), 1.f);   // fp_map
        avb[VRD*VRD]         = fminf(fmaxf(all, 0.f), 1.f);   // fp_exp
        avb[18*VRD*VRD]      = fminf(fmaxf(as , 0.f), 1.f);   // fp_stair
    }
    if (lane < 16)
        avb[(size_t)(2+lane)*VRD*VRD] = fminf(fmaxf(s/5.0f, 0.f), 1.f);
}

// ---------------- K5: rotation grid_sample ----------------
__device__ __forceinline__ float av_fetch(int b, int ch, int ix, int iy)
{
    if (iy < 240 || iy >= 340 || ix < 190 || ix >= 290) return 0.f;
    return g_av[(b*AVC + ch)*(VRD*VRD) + (iy-240)*VRD + (ix-190)];
}

__global__ void __launch_bounds__(256) k_rot()
{
    int idx = blockIdx.x*blockDim.x + threadIdx.x;
    if (idx >= BSZ*NPIX) return;
    int b = idx / NPIX;
    int p = idx - b*NPIX;
    int h = p / MSZ, w = p - h*MSZ;
    float ct = g_par[b][0], st = g_par[b][1];
    float gx = ((float)w + 0.5f)*2.0f/480.0f - 1.0f;
    float gy = ((float)h + 0.5f)*2.0f/480.0f - 1.0f;
    float u = ct*gx - st*gy;
    float v = st*gx + ct*gy;
    float x = (u + 1.0f)*0.5f*479.0f;
    float y = (v + 1.0f)*0.5f*479.0f;
    float x0f = floorf(x), y0f = floorf(y);
    int x0 = (int)x0f, y0 = (int)y0f;
    float wx = x - x0f, wy = y - y0f;
    float* out = g_rot + (size_t)b*AVC*NPIX + p;
    if (x0+1 < 190 || x0 > 289 || y0+1 < 240 || y0 > 339) {
        #pragma unroll
        for (int ch = 0; ch < AVC; ++ch) out[(size_t)ch*NPIX] = 0.f;
        return;
    }
    float w00 = (1.f-wx)*(1.f-wy), w10 = wx*(1.f-wy);
    float w01 = (1.f-wx)*wy,       w11 = wx*wy;
    #pragma unroll
    for (int ch = 0; ch < AVC; ++ch) {
        float val = w00*av_fetch(b,ch,x0,  y0  )
                  + w10*av_fetch(b,ch,x0+1,y0  )
                  + w01*av_fetch(b,ch,x0,  y0+1)
                  + w11*av_fetch(b,ch,x0+1,y0+1);
        out[(size_t)ch*NPIX] = val;
    }
}

// ---------------- K6: translation grid_sample -> translated ----------------
__global__ void __launch_bounds__(256) k_trans(float* __restrict__ translated)
{
    int idx = blockIdx.x*blockDim.x + threadIdx.x;
    if (idx >= BSZ*NPIX) return;
    int b = idx / NPIX;
    int p = idx - b*NPIX;
    int h = p / MSZ, w = p - h*MSZ;
    float sx = g_par[b][2], sy = g_par[b][3];
    float gx = ((float)w + 0.5f)*2.0f/480.0f - 1.0f;
    float gy = ((float)h + 0.5f)*2.0f/480.0f - 1.0f;
    float x = (gx + sx + 1.0f)*0.5f*479.0f;
    float y = (gy + sy + 1.0f)*0.5f*479.0f;
    float x0f = floorf(x), y0f = floorf(y);
    int x0 = (int)x0f, y0 = (int)y0f;
    float wx = x - x0f, wy = y - y0f;

    float* to = translated + (size_t)b*CC*NPIX + p;
    float res[AVC];
    bool any = !(x0+1 < 0 || x0 > 479 || y0+1 < 0 || y0 > 479);
    if (!any) {
        #pragma unroll
        for (int ch = 0; ch < AVC; ++ch) res[ch] = 0.f;
    } else {
        bool vx0 = (x0   >= 0 && x0   < 480);
        bool vx1 = (x0+1 >= 0 && x0+1 < 480);
        bool vy0 = (y0   >= 0 && y0   < 480);
        bool vy1 = (y0+1 >= 0 && y0+1 < 480);
        float w00 = (1.f-wx)*(1.f-wy), w10 = wx*(1.f-wy);
        float w01 = (1.f-wx)*wy,       w11 = wx*wy;
        const float* rb = g_rot + (size_t)b*AVC*NPIX;
        #pragma unroll
        for (int ch = 0; ch < AVC; ++ch) {
            const float* rc = rb + (size_t)ch*NPIX;
            float v00 = (vx0 && vy0) ? rc[y0*MSZ + x0]         : 0.f;
            float v10 = (vx1 && vy0) ? rc[y0*MSZ + x0 + 1]     : 0.f;
            float v01 = (vx0 && vy1) ? rc[(y0+1)*MSZ + x0]     : 0.f;
            float v11 = (vx1 && vy1) ? rc[(y0+1)*MSZ + x0 + 1] : 0.f;
            res[ch] = w00*v00 + w10*v10 + w01*v01 + w11*v11;
        }
    }
    to[0]              = res[0];
    to[(size_t)NPIX]   = res[1];
    to[(size_t)2*NPIX] = 0.f;
    to[(size_t)3*NPIX] = 0.f;
    #pragma unroll
    for (int k = 0; k < 16; ++k)
        to[(size_t)(4+k)*NPIX] = res[2+k];
    g_ts0[(size_t)b*NPIX + p] = res[18];
}

// ---------------- K7: maxpool + kill + map fusion ----------------
__global__ void __launch_bounds__(256) k_final(const float* __restrict__ maps_last,
                                               const float* __restrict__ eve_angle,
                                               const float* __restrict__ translated,
                                               float* __restrict__ map_pred,
                                               float* __restrict__ map_pred_stair)
{
    int idx = blockIdx.x*blockDim.x + threadIdx.x;
    if (idx >= BSZ*NPIX) return;
    int b = idx / NPIX;
    int p = idx - b*NPIX;
    int h = p / MSZ, w = p - h*MSZ;

    const float* tb = translated + (size_t)b*CC*NPIX;
    float mp = -INFINITY;
    #pragma unroll
    for (int dy = -1; dy <= 1; ++dy) {
        int hy = h + dy;
        if (hy < 0 || hy >= MSZ) continue;
        #pragma unroll
        for (int dx = -1; dx <= 1; ++dx) {
            int wx = w + dx;
            if (wx < 0 || wx >= MSZ) continue;
            mp = fmaxf(mp, tb[hy*MSZ + wx]);
        }
    }
    float t1v = tb[(size_t)NPIX + p];
    bool eve0 = (eve_angle[b] == 0.0f);
    bool kill = ((t1v - mp) > 0.8f) && eve0;

    float ts0 = g_ts0[(size_t)b*NPIX + p];
    float ts1 = t1v;
    if (b == 0) {
        float sm = 0.f;
        int ys0 = g_sc[1] - 30, xs0 = g_sc[0] - 30;
        int ii = h - ys0, jj = w - xs0;
        if (ii >= 0 && ii < 60 && jj >= 0 && jj < 60) {
            float di = (float)ii + 0.5f - 30.0f;
            float dj = (float)jj + 0.5f - 30.0f;
            if (di*di + dj*dj <= 900.0f) sm = 1.0f;
        }
        ts0 *= sm; ts1 *= sm;
    }
    bool kill_s = ((ts1 - ts0) > 0.8f) && eve0;

    const float* ml = maps_last + (size_t)b*CC*NPIX + p;
    float* mo = map_pred       + (size_t)b*CC*NPIX + p;
    float* so = map_pred_stair + (size_t)b*CC*NPIX + p;
    #pragma unroll
    for (int c = 0; c < CC; ++c) {
        float t  = tb[(size_t)c*NPIX + p];
        float m  = ml[(size_t)c*NPIX];
        float mv = fmaxf(m, t);
        float ts = (c == 0) ? ts0 : (c == 1) ? ts1 : t;
        float sv = fmaxf(m, ts);
        if (c == 0) {
            if (kill)   mv = 0.f;
            if (kill_s) sv = 0.f;
        }
        mo[(size_t)c*NPIX] = mv;
        so[(size_t)c*NPIX] = sv;
    }
}

// ---------------- launch ----------------
extern "C" void kernel_launch(void* const* d_in, const int* in_sizes, int n_in,
                              void* d_out, int out_size)
{
    const float* obs        = (const float*)d_in[0];
    const float* pose_obs   = (const float*)d_in[1];
    const float* maps_last  = (const float*)d_in[2];
    const float* poses_last = (const float*)d_in[3];
    const float* eve_angle  = (const float*)d_in[4];
    float* out = (float*)d_out;

    float* translated     = out;
    float* map_pred       = out + (size_t)BSZ*CC*NPIX;
    float* map_pred_stair = out + 2*(size_t)BSZ*CC*NPIX;
    float* out_poses      = out + 3*(size_t)BSZ*CC*NPIX;

    k_pose<<<1, 32>>>(pose_obs, poses_last, eve_angle, out_poses);
    k_zero<<<(VOX_TOTAL/4 + 255)/256, 256>>>();
    k_splat<<<(BSZ*HH*WW + 255)/256, 256>>>(obs);
    k_reduce<<<(NCELL*32 + 255)/256, 256>>>();
    k_rot<<<(BSZ*NPIX + 255)/256, 256>>>();
    k_trans<<<(BSZ*NPIX + 255)/256, 256>>>(translated);
    k_final<<<(BSZ*NPIX + 255)/256, 256>>>(maps_last, eve_angle, translated,
                                           map_pred, map_pred_stair);
}

// round 3
// speedup vs baseline: 2.1131x; 1.0157x over previous
#include <cuda_runtime.h>
#include <math.h>

#define BSZ 4
#define HH 480
#define WW 640
#define CC 20
#define MSZ 480
#define VRD 100
#define NZD 48
#define SEMZ0 13
#define SEMZ1 35
#define CELLF 400             // 48 occ + 22*16 sem floats per (b,x,y) cell
#define AVC 19                // 0:fp_map 1:fp_exp 2..17:sem 18:fp_stair
#define NPIX (MSZ*MSZ)
#define NCELL (BSZ*VRD*VRD)
#define VOX_TOTAL (NCELL*CELLF)
#define RX0 124               // rotated-nonzero region [124,356) x [124,356)
#define RSZ 232

// ---------------- device scratch (static, no allocation) ----------------
__device__ float4 g_vox4[VOX_TOTAL/4];             // 64 MB, zero-init at load,
                                                   // re-zeroed by k_reduce each run
__device__ float  g_av [BSZ*AVC*VRD*VRD];
__device__ float  g_rot[BSZ*AVC*RSZ*RSZ];          // 16.4 MB compact rotated image
__device__ float  g_par[BSZ][6];                   // ct, st, sx, sy, ca, sa
__device__ float  g_F;
__device__ int    g_sc[2];

__device__ __forceinline__ void red_add_v4(float* p, float a, float b, float c, float d)
{
    asm volatile("red.global.add.v4.f32 [%0], {%1, %2, %3, %4};"
                 :: "l"(p), "f"(a), "f"(b), "f"(c), "f"(d) : "memory");
}
__device__ __forceinline__ void red_add_f32(float* p, float v)
{
    asm volatile("red.global.add.f32 [%0], %1;" :: "l"(p), "f"(v) : "memory");
}

// ---------------- K1: pose + params ----------------
__global__ void k_pose(const float* __restrict__ pose_obs,
                       const float* __restrict__ poses_last,
                       const float* __restrict__ eve_angle,
                       float* __restrict__ out_poses)
{
    int b = threadIdx.x;
    if (b >= BSZ) return;
    const float R2D = 57.29577951308232f;
    float px = poses_last[b*3+0];
    float py = poses_last[b*3+1];
    float pt = poses_last[b*3+2];
    float r = pt / R2D;
    float sr, cr; sincosf(r, &sr, &cr);
    float ox = pose_obs[b*3+0], oy = pose_obs[b*3+1], ot = pose_obs[b*3+2];
    float ny = py + ox*sr + oy*cr;
    float nx = px + ox*cr - oy*sr;
    float nt = pt + ot*R2D;
    nt = fmodf(nt - 180.0f, 360.0f) + 180.0f;
    nt = fmodf(nt + 180.0f, 360.0f) - 180.0f;
    out_poses[b*3+0] = nx;
    out_poses[b*3+1] = ny;
    out_poses[b*3+2] = nt;

    const float half = 240.0f;
    float sx = (half - nx*100.0f/5.0f)/half;
    float sy = (half - ny*100.0f/5.0f)/half;
    float t = (90.0f - nt) * (float)(M_PI/180.0);
    float st, ct; sincosf(t, &st, &ct);
    float a = eve_angle[b] * (float)(M_PI/180.0);
    float sa, ca; sincosf(a, &sa, &ca);
    g_par[b][0] = ct; g_par[b][1] = st;
    g_par[b][2] = sx; g_par[b][3] = sy;
    g_par[b][4] = ca; g_par[b][5] = sa;
    if (b == 0) {
        g_F = (float)(320.0 / tan(39.5 * M_PI / 180.0));
        int sxi = (int)(nx * 100.0f / 5.0f);
        int syi = (int)(ny * 100.0f / 5.0f);
        sxi = min(max(sxi, 30), MSZ - 30 - 1);
        syi = min(max(syi, 30), MSZ - 30 - 1);
        g_sc[0] = sxi; g_sc[1] = syi;
    }
}

// ---------------- K3: trilinear splat (vector reds, packed z) ----------------
__global__ void __launch_bounds__(256) k_splat(const float* __restrict__ obs)
{
    int idx = blockIdx.x*blockDim.x + threadIdx.x;
    if (idx >= BSZ*HH*WW) return;
    int b   = idx / (HH*WW);
    int pix = idx - b*(HH*WW);
    int i   = pix / WW;
    int j   = pix - i*WW;

    float F  = g_F;
    float ca = g_par[b][4], sa = g_par[b][5];
    const float* ob = obs + (size_t)b*CC*HH*WW;
    float d  = ob[(3*HH + i)*WW + j];

    float X  = ((float)j - 319.5f) * d / F + 250.0f;
    float Zc = ((float)(HH-1-i) - 239.5f) * d / F;
    float Y  = ca*d - sa*Zc;
    float Z  = sa*d + ca*Zc + 88.0f;

    float xs = ((X/5.0f - 50.0f)/100.0f)*2.0f;
    float ys = ((Y/5.0f - 50.0f)/100.0f)*2.0f;
    float zs = ((Z/5.0f - 16.0f)/48.0f)*2.0f;
    float p0 = xs*50.0f + 50.0f;
    float p1 = ys*50.0f + 50.0f;
    float p2 = zs*24.0f + 24.0f;

    float f0 = floorf(p0), f1 = floorf(p1), f2 = floorf(p2);
    if (f0 <= -1.0f || f0 >= 100.0f) return;
    if (f1 <= -1.0f || f1 >= 100.0f) return;
    if (f2 <= -1.0f || f2 >= 48.0f)  return;

    // z-corner weights/validity (at least one corner valid after the early-outs)
    int   z0  = (int)f2;                       // 0..47
    float wz0 = 1.0f - fabsf(p2 - f2);
    float wz1 = 1.0f - fabsf(p2 - (f2 + 1.0f));
    bool  z0v = (f2 > 0.0f);                   // f2 < 48 guaranteed
    bool  z1v = (f2 < 47.0f);                  // f2+1 > 0 guaranteed (f2 >= 0 here)
    float a0  = z0v ? wz0 : 0.f;
    float a1  = z1v ? wz1 : 0.f;

    // packed occupancy v4 pattern covering z0 and z0+1
    int q = z0 & ~3;
    int s = z0 & 3;
    float u0 = (s==0) ? a0 : 0.f;
    float u1 = (s==1) ? a0 : (s==0 ? a1 : 0.f);
    float u2 = (s==2) ? a0 : (s==1 ? a1 : 0.f);
    float u3 = (s==3) ? a0 : (s==2 ? a1 : 0.f);
    bool spill = (s==3) && (a1 != 0.f);

    bool sem0 = z0v && (z0 >= SEMZ0) && (z0 < SEMZ1);
    bool sem1 = z1v && (z0+1 >= SEMZ0) && (z0+1 < SEMZ1);

    float sem[16];
    if (sem0 || sem1) {
        #pragma unroll
        for (int c = 0; c < 16; ++c)
            sem[c] = ob[((4+c)*HH + i)*WW + j];
    }

    float* vox = reinterpret_cast<float*>(g_vox4);
    #pragma unroll
    for (int ix = 0; ix < 2; ++ix) {
        float xf = f0 + (float)ix;
        if (!(xf > 0.0f && xf < 100.0f)) continue;
        float wx = 1.0f - fabsf(p0 - xf);
        int xi = (int)xf;
        #pragma unroll
        for (int iy = 0; iy < 2; ++iy) {
            float yf = f1 + (float)iy;
            if (!(yf > 0.0f && yf < 100.0f)) continue;
            float wxy = wx * (1.0f - fabsf(p1 - yf));
            int yi = (int)yf;
            float* cellp = vox + (size_t)((b*VRD + xi)*VRD + yi)*CELLF;

            // occupancy: one v4 (plus rare spill)
            red_add_v4(cellp + q, wxy*u0, wxy*u1, wxy*u2, wxy*u3);
            if (spill) red_add_f32(cellp + z0 + 1, wxy*a1);

            // semantics
            if (sem0) {
                float f = wxy * wz0;
                float* sp = cellp + NZD + (z0 - SEMZ0)*16;
                red_add_v4(sp     , f*sem[0],  f*sem[1],  f*sem[2],  f*sem[3]);
                red_add_v4(sp + 4 , f*sem[4],  f*sem[5],  f*sem[6],  f*sem[7]);
                red_add_v4(sp + 8 , f*sem[8],  f*sem[9],  f*sem[10], f*sem[11]);
                red_add_v4(sp + 12, f*sem[12], f*sem[13], f*sem[14], f*sem[15]);
            }
            if (sem1) {
                float f = wxy * wz1;
                float* sp = cellp + NZD + (z0 + 1 - SEMZ0)*16;
                red_add_v4(sp     , f*sem[0],  f*sem[1],  f*sem[2],  f*sem[3]);
                red_add_v4(sp + 4 , f*sem[4],  f*sem[5],  f*sem[6],  f*sem[7]);
                red_add_v4(sp + 8 , f*sem[8],  f*sem[9],  f*sem[10], f*sem[11]);
                red_add_v4(sp + 12, f*sem[12], f*sem[13], f*sem[14], f*sem[15]);
            }
        }
    }
}

// ---------------- K4: warp-per-cell reduce + re-zero ----------------
__global__ void __launch_bounds__(256) k_reduce()
{
    int warp = (blockIdx.x*blockDim.x + threadIdx.x) >> 5;
    int lane = threadIdx.x & 31;
    if (warp >= NCELL) return;
    int b  = warp / (VRD*VRD);
    int r  = warp - b*(VRD*VRD);
    int xi = r / VRD;
    int yi = r - xi*VRD;
    float* v = reinterpret_cast<float*>(g_vox4) + (size_t)warp*CELLF;

    // occupancy windows
    float o1 = rintf(v[lane]);
    float o2 = (lane < 16) ? rintf(v[32 + lane]) : 0.f;
    float all = o1 + o2;
    float ah  = ((lane >= 13) ? o1 : 0.f) + ((lane < 3) ? o2 : 0.f);
    float as  = (lane >= 20 && lane < 25) ? o1 : 0.f;

    // semantic sums: lanes 0-15 -> z 0..10, lanes 16-31 -> z 11..21 (per channel)
    int c = lane & 15;
    int halfw = lane >> 4;
    float s = 0.f;
    const float* sv = v + NZD + c;
    #pragma unroll
    for (int t = 0; t < 11; ++t)
        s += rintf(sv[(halfw*11 + t)*16]);

    // re-zero the cell for the next launch (reads above are complete per-lane;
    // sync the warp so no lane's zero-store races another lane's pending read)
    __syncwarp();
    float4* cz = reinterpret_cast<float4*>(v);
    float4 z4 = make_float4(0.f, 0.f, 0.f, 0.f);
    #pragma unroll
    for (int k = lane; k < CELLF/4; k += 32) cz[k] = z4;

    s += __shfl_xor_sync(0xffffffffu, s, 16);
    #pragma unroll
    for (int off = 16; off; off >>= 1) {
        all += __shfl_xor_sync(0xffffffffu, all, off);
        ah  += __shfl_xor_sync(0xffffffffu, ah , off);
        as  += __shfl_xor_sync(0xffffffffu, as , off);
    }

    float* avb = g_av + (size_t)b*AVC*VRD*VRD + yi*VRD + xi;
    if (lane == 0) {
        avb[0]          = fminf(fmaxf(ah , 0.f), 1.f);
        avb[VRD*VRD]    = fminf(fmaxf(all, 0.f), 1.f);
        avb[18*VRD*VRD] = fminf(fmaxf(as , 0.f), 1.f);
    }
    if (lane < 16)
        avb[(size_t)(2+lane)*VRD*VRD] = fminf(fmaxf(s/5.0f, 0.f), 1.f);
}

// ---------------- K5: rotation grid_sample (compact region only) ----------------
__device__ __forceinline__ float av_fetch(int b, int ch, int ix, int iy)
{
    if (iy < 240 || iy >= 340 || ix < 190 || ix >= 290) return 0.f;
    return g_av[(b*AVC + ch)*(VRD*VRD) + (iy-240)*VRD + (ix-190)];
}

__global__ void __launch_bounds__(256) k_rot()
{
    int idx = blockIdx.x*blockDim.x + threadIdx.x;
    if (idx >= BSZ*RSZ*RSZ) return;
    int b = idx / (RSZ*RSZ);
    int p = idx - b*(RSZ*RSZ);
    int h = p / RSZ + RX0, w = p - (p / RSZ)*RSZ + RX0;
    float ct = g_par[b][0], st = g_par[b][1];
    float gx = ((float)w + 0.5f)*2.0f/480.0f - 1.0f;
    float gy = ((float)h + 0.5f)*2.0f/480.0f - 1.0f;
    float u = ct*gx - st*gy;
    float v = st*gx + ct*gy;
    float x = (u + 1.0f)*0.5f*479.0f;
    float y = (v + 1.0f)*0.5f*479.0f;
    float x0f = floorf(x), y0f = floorf(y);
    int x0 = (int)x0f, y0 = (int)y0f;
    float wx = x - x0f, wy = y - y0f;
    float* out = g_rot + ((size_t)b*AVC)*RSZ*RSZ + p;
    if (x0+1 < 190 || x0 > 289 || y0+1 < 240 || y0 > 339) {
        #pragma unroll
        for (int ch = 0; ch < AVC; ++ch) out[(size_t)ch*RSZ*RSZ] = 0.f;
        return;
    }
    float w00 = (1.f-wx)*(1.f-wy), w10 = wx*(1.f-wy);
    float w01 = (1.f-wx)*wy,       w11 = wx*wy;
    #pragma unroll
    for (int ch = 0; ch < AVC; ++ch) {
        float val = w00*av_fetch(b,ch,x0,  y0  )
                  + w10*av_fetch(b,ch,x0+1,y0  )
                  + w01*av_fetch(b,ch,x0,  y0+1)
                  + w11*av_fetch(b,ch,x0+1,y0+1);
        out[(size_t)ch*RSZ*RSZ] = val;
    }
}

// ---------------- K6: fused translation + maxpool/kill/map fusion ----------------
__device__ __forceinline__ float rot_fetch(int b, int ch, int ix, int iy)
{
    if (ix < RX0 || ix >= RX0+RSZ || iy < RX0 || iy >= RX0+RSZ) return 0.f;
    return g_rot[((size_t)(b*AVC + ch)*RSZ + (iy-RX0))*RSZ + (ix-RX0)];
}

__device__ __forceinline__ float sample_ch(int b, int ch, int h, int w,
                                           float sx, float sy)
{
    float gx = ((float)w + 0.5f)*2.0f/480.0f - 1.0f;
    float gy = ((float)h + 0.5f)*2.0f/480.0f - 1.0f;
    float x = (gx + sx + 1.0f)*0.5f*479.0f;
    float y = (gy + sy + 1.0f)*0.5f*479.0f;
    float x0f = floorf(x), y0f = floorf(y);
    int x0 = (int)x0f, y0 = (int)y0f;
    float wx = x - x0f, wy = y - y0f;
    float w00 = (1.f-wx)*(1.f-wy), w10 = wx*(1.f-wy);
    float w01 = (1.f-wx)*wy,       w11 = wx*wy;
    return w00*rot_fetch(b,ch,x0,  y0  )
         + w10*rot_fetch(b,ch,x0+1,y0  )
         + w01*rot_fetch(b,ch,x0,  y0+1)
         + w11*rot_fetch(b,ch,x0+1,y0+1);
}

__global__ void __launch_bounds__(256) k_tf(const float* __restrict__ maps_last,
                                            const float* __restrict__ eve_angle,
                                            float* __restrict__ translated,
                                            float* __restrict__ map_pred,
                                            float* __restrict__ map_pred_stair)
{
    __shared__ float s0[18][19];
    int b  = blockIdx.z;
    int w0 = blockIdx.x*16, h0 = blockIdx.y*16;
    int tid = threadIdx.y*16 + threadIdx.x;
    float sx = g_par[b][2], sy = g_par[b][3];

    // halo ch0 (18x18)
    for (int t = tid; t < 324; t += 256) {
        int i = t / 18, j = t - (t/18)*18;
        int hh = h0 - 1 + i, ww = w0 - 1 + j;
        float val = -INFINITY;
        if (hh >= 0 && hh < MSZ && ww >= 0 && ww < MSZ)
            val = sample_ch(b, 0, hh, ww, sx, sy);
        s0[i][j] = val;
    }
    __syncthreads();

    int w = w0 + threadIdx.x, h = h0 + threadIdx.y;
    int p = h*MSZ + w;

    // full 19-channel sample (shared coords computed once)
    float gx = ((float)w + 0.5f)*2.0f/480.0f - 1.0f;
    float gy = ((float)h + 0.5f)*2.0f/480.0f - 1.0f;
    float x = (gx + sx + 1.0f)*0.5f*479.0f;
    float y = (gy + sy + 1.0f)*0.5f*479.0f;
    float x0f = floorf(x), y0f = floorf(y);
    int x0 = (int)x0f, y0 = (int)y0f;
    float wx = x - x0f, wy = y - y0f;
    float w00 = (1.f-wx)*(1.f-wy), w10 = wx*(1.f-wy);
    float w01 = (1.f-wx)*wy,       w11 = wx*wy;

    float res[AVC];
    #pragma unroll
    for (int ch = 0; ch < AVC; ++ch) {
        res[ch] = w00*rot_fetch(b,ch,x0,  y0  )
                + w10*rot_fetch(b,ch,x0+1,y0  )
                + w01*rot_fetch(b,ch,x0,  y0+1)
                + w11*rot_fetch(b,ch,x0+1,y0+1);
    }

    // write translated (output 0)
    float* to = translated + (size_t)b*CC*NPIX + p;
    to[0]              = res[0];
    to[(size_t)NPIX]   = res[1];
    to[(size_t)2*NPIX] = 0.f;
    to[(size_t)3*NPIX] = 0.f;
    #pragma unroll
    for (int k = 0; k < 16; ++k)
        to[(size_t)(4+k)*NPIX] = res[2+k];

    // maxpool 3x3 over ch0 from smem halo
    int ty = threadIdx.y, tx = threadIdx.x;
    float mp = -INFINITY;
    #pragma unroll
    for (int dy = 0; dy < 3; ++dy)
        #pragma unroll
        for (int dx = 0; dx < 3; ++dx)
            mp = fmaxf(mp, s0[ty+dy][tx+dx]);

    float t1v = res[1];
    bool eve0 = (eve_angle[b] == 0.0f);
    bool kill = ((t1v - mp) > 0.8f) && eve0;

    float ts0 = res[18];
    float ts1 = t1v;
    if (b == 0) {
        float sm = 0.f;
        int ys0 = g_sc[1] - 30, xs0 = g_sc[0] - 30;
        int ii = h - ys0, jj = w - xs0;
        if (ii >= 0 && ii < 60 && jj >= 0 && jj < 60) {
            float di = (float)ii + 0.5f - 30.0f;
            float dj = (float)jj + 0.5f - 30.0f;
            if (di*di + dj*dj <= 900.0f) sm = 1.0f;
        }
        ts0 *= sm; ts1 *= sm;
    }
    bool kill_s = ((ts1 - ts0) > 0.8f) && eve0;

    const float* ml = maps_last + (size_t)b*CC*NPIX + p;
    float* mo = map_pred       + (size_t)b*CC*NPIX + p;
    float* so = map_pred_stair + (size_t)b*CC*NPIX + p;
    #pragma unroll
    for (int c = 0; c < CC; ++c) {
        float t  = (c == 0) ? res[0] : (c == 1) ? res[1]
                 : (c < 4)  ? 0.f    : res[c-2];
        float m  = ml[(size_t)c*NPIX];
        float mv = fmaxf(m, t);
        float ts = (c == 0) ? ts0 : (c == 1) ? ts1 : t;
        float sv = fmaxf(m, ts);
        if (c == 0) {
            if (kill)   mv = 0.f;
            if (kill_s) sv = 0.f;
        }
        mo[(size_t)c*NPIX] = mv;
        so[(size_t)c*NPIX] = sv;
    }
}

// ---------------- launch ----------------
extern "C" void kernel_launch(void* const* d_in, const int* in_sizes, int n_in,
                              void* d_out, int out_size)
{
    const float* obs        = (const float*)d_in[0];
    const float* pose_obs   = (const float*)d_in[1];
    const float* maps_last  = (const float*)d_in[2];
    const float* poses_last = (const float*)d_in[3];
    const float* eve_angle  = (const float*)d_in[4];
    float* out = (float*)d_out;

    float* translated     = out;
    float* map_pred       = out + (size_t)BSZ*CC*NPIX;
    float* map_pred_stair = out + 2*(size_t)BSZ*CC*NPIX;
    float* out_poses      = out + 3*(size_t)BSZ*CC*NPIX;

    k_pose<<<1, 32>>>(pose_obs, poses_last, eve_angle, out_poses);
    k_splat<<<(BSZ*HH*WW + 255)/256, 256>>>(obs);
    k_reduce<<<(NCELL*32 + 255)/256, 256>>>();
    k_rot<<<(BSZ*RSZ*RSZ + 255)/256, 256>>>();
    dim3 tfgrid(MSZ/16, MSZ/16, BSZ);
    dim3 tfblock(16, 16);
    k_tf<<<tfgrid, tfblock>>>(maps_last, eve_angle, translated,
                              map_pred, map_pred_stair);
}

// round 8
// speedup vs baseline: 2.3652x; 1.1193x over previous
#include <cuda_runtime.h>
#include <math.h>

#define BSZ 4
#define HH 480
#define WW 640
#define CC 20
#define MSZ 480
#define VRD 100
#define NZD 48
#define SEMZ0 13
#define SEMZ1 35
#define CELLF 400             // 48 occ + 22*16 sem floats per (b,x,y) cell
#define AVC 19                // 0:fp_map 1:fp_exp 2..17:sem 18:fp_stair
#define NPIX (MSZ*MSZ)
#define NCELL (BSZ*VRD*VRD)
#define VOX_TOTAL (NCELL*CELLF)
#define RX0 124               // rotated-nonzero region [124,356) x [124,356)
#define RSZ 232

// ---------------- device scratch (static, no allocation) ----------------
__device__ float4 g_vox4[VOX_TOTAL/4];             // zero-init at load; k_reduce re-zeros
__device__ float  g_av [BSZ*AVC*VRD*VRD];
__device__ float  g_rot[BSZ*AVC*RSZ*RSZ];
__device__ float  g_par[BSZ][6];                   // ct, st, sx, sy, ca, sa
__device__ float  g_F;
__device__ int    g_sc[2];

__device__ __forceinline__ void red_add_v4(float* p, float a, float b, float c, float d)
{
    asm volatile("red.global.add.v4.f32 [%0], {%1, %2, %3, %4};"
                 :: "l"(p), "f"(a), "f"(b), "f"(c), "f"(d) : "memory");
}
__device__ __forceinline__ void red_add_f32(float* p, float v)
{
    asm volatile("red.global.add.f32 [%0], %1;" :: "l"(p), "f"(v) : "memory");
}

// ---------------- K1: pose + params ----------------
__global__ void k_pose(const float* __restrict__ pose_obs,
                       const float* __restrict__ poses_last,
                       const float* __restrict__ eve_angle,
                       float* __restrict__ out_poses)
{
    int b = threadIdx.x;
    if (b >= BSZ) return;
    const float R2D = 57.29577951308232f;
    float px = poses_last[b*3+0];
    float py = poses_last[b*3+1];
    float pt = poses_last[b*3+2];
    float r = pt / R2D;
    float sr, cr; sincosf(r, &sr, &cr);
    float ox = pose_obs[b*3+0], oy = pose_obs[b*3+1], ot = pose_obs[b*3+2];
    float ny = py + ox*sr + oy*cr;
    float nx = px + ox*cr - oy*sr;
    float nt = pt + ot*R2D;
    nt = fmodf(nt - 180.0f, 360.0f) + 180.0f;
    nt = fmodf(nt + 180.0f, 360.0f) - 180.0f;
    out_poses[b*3+0] = nx;
    out_poses[b*3+1] = ny;
    out_poses[b*3+2] = nt;

    const float half = 240.0f;
    float sx = (half - nx*100.0f/5.0f)/half;
    float sy = (half - ny*100.0f/5.0f)/half;
    float t = (90.0f - nt) * (float)(M_PI/180.0);
    float st, ct; sincosf(t, &st, &ct);
    float a = eve_angle[b] * (float)(M_PI/180.0);
    float sa, ca; sincosf(a, &sa, &ca);
    g_par[b][0] = ct; g_par[b][1] = st;
    g_par[b][2] = sx; g_par[b][3] = sy;
    g_par[b][4] = ca; g_par[b][5] = sa;
    if (b == 0) {
        g_F = (float)(320.0 / tan(39.5 * M_PI / 180.0));
        int sxi = (int)(nx * 100.0f / 5.0f);
        int syi = (int)(ny * 100.0f / 5.0f);
        sxi = min(max(sxi, 30), MSZ - 30 - 1);
        syi = min(max(syi, 30), MSZ - 30 - 1);
        g_sc[0] = sxi; g_sc[1] = syi;
    }
}

// ---------------- K3: per-batch trilinear splat ----------------
__global__ void __launch_bounds__(256) k_splat(const float* __restrict__ obs, int b)
{
    int pix = blockIdx.x*blockDim.x + threadIdx.x;
    if (pix >= HH*WW) return;
    int i   = pix / WW;
    int j   = pix - i*WW;

    float F  = g_F;
    float ca = g_par[b][4], sa = g_par[b][5];
    const float* ob = obs + (size_t)b*CC*HH*WW;
    float d  = ob[(3*HH + i)*WW + j];

    float X  = ((float)j - 319.5f) * d / F + 250.0f;
    float Zc = ((float)(HH-1-i) - 239.5f) * d / F;
    float Y  = ca*d - sa*Zc;
    float Z  = sa*d + ca*Zc + 88.0f;

    float xs = ((X/5.0f - 50.0f)/100.0f)*2.0f;
    float ys = ((Y/5.0f - 50.0f)/100.0f)*2.0f;
    float zs = ((Z/5.0f - 16.0f)/48.0f)*2.0f;
    float p0 = xs*50.0f + 50.0f;
    float p1 = ys*50.0f + 50.0f;
    float p2 = zs*24.0f + 24.0f;

    float f0 = floorf(p0), f1 = floorf(p1), f2 = floorf(p2);
    if (f0 <= -1.0f || f0 >= 100.0f) return;
    if (f1 <= -1.0f || f1 >= 100.0f) return;
    if (f2 <= -1.0f || f2 >= 48.0f)  return;

    int   z0  = (int)f2;
    float wz0 = 1.0f - fabsf(p2 - f2);
    float wz1 = 1.0f - fabsf(p2 - (f2 + 1.0f));
    bool  z0v = (f2 > 0.0f);
    bool  z1v = (f2 < 47.0f);
    float a0  = z0v ? wz0 : 0.f;
    float a1  = z1v ? wz1 : 0.f;

    bool sem0 = z0v && (z0 >= SEMZ0) && (z0 < SEMZ1);
    bool sem1 = z1v && (z0+1 >= SEMZ0) && (z0+1 < SEMZ1);

    float sem[16];
    if (sem0 || sem1) {
        #pragma unroll
        for (int c = 0; c < 16; ++c)
            sem[c] = ob[((4+c)*HH + i)*WW + j];
    }

    float* vox = reinterpret_cast<float*>(g_vox4);
    #pragma unroll
    for (int ix = 0; ix < 2; ++ix) {
        float xf = f0 + (float)ix;
        if (!(xf > 0.0f && xf < 100.0f)) continue;
        float wx = 1.0f - fabsf(p0 - xf);
        int xi = (int)xf;
        #pragma unroll
        for (int iy = 0; iy < 2; ++iy) {
            float yf = f1 + (float)iy;
            if (!(yf > 0.0f && yf < 100.0f)) continue;
            float wxy = wx * (1.0f - fabsf(p1 - yf));
            int yi = (int)yf;
            float* cellp = vox + (size_t)((b*VRD + xi)*VRD + yi)*CELLF;

            // occupancy: guarded scalar reds (z0, z0+1 share a sector)
            if (a0 > 0.f) red_add_f32(cellp + z0,     wxy*a0);
            if (a1 > 0.f) red_add_f32(cellp + z0 + 1, wxy*a1);

            if (sem0) {
                float f = wxy * wz0;
                float* sp = cellp + NZD + (z0 - SEMZ0)*16;
                red_add_v4(sp     , f*sem[0],  f*sem[1],  f*sem[2],  f*sem[3]);
                red_add_v4(sp + 4 , f*sem[4],  f*sem[5],  f*sem[6],  f*sem[7]);
                red_add_v4(sp + 8 , f*sem[8],  f*sem[9],  f*sem[10], f*sem[11]);
                red_add_v4(sp + 12, f*sem[12], f*sem[13], f*sem[14], f*sem[15]);
            }
            if (sem1) {
                float f = wxy * wz1;
                float* sp = cellp + NZD + (z0 + 1 - SEMZ0)*16;
                red_add_v4(sp     , f*sem[0],  f*sem[1],  f*sem[2],  f*sem[3]);
                red_add_v4(sp + 4 , f*sem[4],  f*sem[5],  f*sem[6],  f*sem[7]);
                red_add_v4(sp + 8 , f*sem[8],  f*sem[9],  f*sem[10], f*sem[11]);
                red_add_v4(sp + 12, f*sem[12], f*sem[13], f*sem[14], f*sem[15]);
            }
        }
    }
}

// ---------------- K4: per-batch warp-per-cell reduce + re-zero ----------------
__global__ void __launch_bounds__(256) k_reduce(int b)
{
    int warp = (blockIdx.x*blockDim.x + threadIdx.x) >> 5;
    int lane = threadIdx.x & 31;
    if (warp >= VRD*VRD) return;
    int xi = warp / VRD;
    int yi = warp - xi*VRD;
    float* v = reinterpret_cast<float*>(g_vox4) + ((size_t)b*VRD*VRD + warp)*CELLF;

    float o1 = rintf(v[lane]);
    float o2 = (lane < 16) ? rintf(v[32 + lane]) : 0.f;
    float all = o1 + o2;
    float ah  = ((lane >= 13) ? o1 : 0.f) + ((lane < 3) ? o2 : 0.f);
    float as  = (lane >= 20 && lane < 25) ? o1 : 0.f;

    int c = lane & 15;
    int halfw = lane >> 4;
    float s = 0.f;
    const float* sv = v + NZD + c;
    #pragma unroll
    for (int t = 0; t < 11; ++t)
        s += rintf(sv[(halfw*11 + t)*16]);

    __syncwarp();
    float4* cz = reinterpret_cast<float4*>(v);
    float4 z4 = make_float4(0.f, 0.f, 0.f, 0.f);
    #pragma unroll
    for (int k = lane; k < CELLF/4; k += 32) cz[k] = z4;

    s += __shfl_xor_sync(0xffffffffu, s, 16);
    #pragma unroll
    for (int off = 16; off; off >>= 1) {
        all += __shfl_xor_sync(0xffffffffu, all, off);
        ah  += __shfl_xor_sync(0xffffffffu, ah , off);
        as  += __shfl_xor_sync(0xffffffffu, as , off);
    }

    float* avb = g_av + (size_t)b*AVC*VRD*VRD + yi*VRD + xi;
    if (lane == 0) {
        avb[0]          = fminf(fmaxf(ah , 0.f), 1.f);
        avb[VRD*VRD]    = fminf(fmaxf(all, 0.f), 1.f);
        avb[18*VRD*VRD] = fminf(fmaxf(as , 0.f), 1.f);
    }
    if (lane < 16)
        avb[(size_t)(2+lane)*VRD*VRD] = fminf(fmaxf(s/5.0f, 0.f), 1.f);
}

// ---------------- K5: per-batch rotation grid_sample ----------------
__device__ __forceinline__ float av_fetch(int b, int ch, int ix, int iy)
{
    if (iy < 240 || iy >= 340 || ix < 190 || ix >= 290) return 0.f;
    return g_av[(b*AVC + ch)*(VRD*VRD) + (iy-240)*VRD + (ix-190)];
}

__global__ void __launch_bounds__(256) k_rot(int b)
{
    int p = blockIdx.x*blockDim.x + threadIdx.x;
    if (p >= RSZ*RSZ) return;
    int h = p / RSZ + RX0, w = p - (p / RSZ)*RSZ + RX0;
    float ct = g_par[b][0], st = g_par[b][1];
    float gx = ((float)w + 0.5f)*2.0f/480.0f - 1.0f;
    float gy = ((float)h + 0.5f)*2.0f/480.0f - 1.0f;
    float u = ct*gx - st*gy;
    float v = st*gx + ct*gy;
    float x = (u + 1.0f)*0.5f*479.0f;
    float y = (v + 1.0f)*0.5f*479.0f;
    float x0f = floorf(x), y0f = floorf(y);
    int x0 = (int)x0f, y0 = (int)y0f;
    float wx = x - x0f, wy = y - y0f;
    float* out = g_rot + ((size_t)b*AVC)*RSZ*RSZ + p;
    if (x0+1 < 190 || x0 > 289 || y0+1 < 240 || y0 > 339) {
        #pragma unroll
        for (int ch = 0; ch < AVC; ++ch) out[(size_t)ch*RSZ*RSZ] = 0.f;
        return;
    }
    float w00 = (1.f-wx)*(1.f-wy), w10 = wx*(1.f-wy);
    float w01 = (1.f-wx)*wy,       w11 = wx*wy;
    #pragma unroll
    for (int ch = 0; ch < AVC; ++ch) {
        float val = w00*av_fetch(b,ch,x0,  y0  )
                  + w10*av_fetch(b,ch,x0+1,y0  )
                  + w01*av_fetch(b,ch,x0,  y0+1)
                  + w11*av_fetch(b,ch,x0+1,y0+1);
        out[(size_t)ch*RSZ*RSZ] = val;
    }
}

// ---------------- K6: per-batch fused translation + maxpool/kill/fusion ----------------
__device__ __forceinline__ float rot_fetch(int b, int ch, int ix, int iy)
{
    if (ix < RX0 || ix >= RX0+RSZ || iy < RX0 || iy >= RX0+RSZ) return 0.f;
    return g_rot[((size_t)(b*AVC + ch)*RSZ + (iy-RX0))*RSZ + (ix-RX0)];
}

__device__ __forceinline__ float sample_ch(int b, int ch, int h, int w,
                                           float sx, float sy)
{
    float gx = ((float)w + 0.5f)*2.0f/480.0f - 1.0f;
    float gy = ((float)h + 0.5f)*2.0f/480.0f - 1.0f;
    float x = (gx + sx + 1.0f)*0.5f*479.0f;
    float y = (gy + sy + 1.0f)*0.5f*479.0f;
    float x0f = floorf(x), y0f = floorf(y);
    int x0 = (int)x0f, y0 = (int)y0f;
    float wx = x - x0f, wy = y - y0f;
    float w00 = (1.f-wx)*(1.f-wy), w10 = wx*(1.f-wy);
    float w01 = (1.f-wx)*wy,       w11 = wx*wy;
    return w00*rot_fetch(b,ch,x0,  y0  )
         + w10*rot_fetch(b,ch,x0+1,y0  )
         + w01*rot_fetch(b,ch,x0,  y0+1)
         + w11*rot_fetch(b,ch,x0+1,y0+1);
}

__global__ void __launch_bounds__(256) k_tf(const float* __restrict__ maps_last,
                                            const float* __restrict__ eve_angle,
                                            float* __restrict__ translated,
                                            float* __restrict__ map_pred,
                                            float* __restrict__ map_pred_stair,
                                            int b)
{
    __shared__ float s0[18][19];
    int w0 = blockIdx.x*16, h0 = blockIdx.y*16;
    int tid = threadIdx.y*16 + threadIdx.x;
    float sx = g_par[b][2], sy = g_par[b][3];

    for (int t = tid; t < 324; t += 256) {
        int i = t / 18, j = t - (t/18)*18;
        int hh = h0 - 1 + i, ww = w0 - 1 + j;
        float val = -INFINITY;
        if (hh >= 0 && hh < MSZ && ww >= 0 && ww < MSZ)
            val = sample_ch(b, 0, hh, ww, sx, sy);
        s0[i][j] = val;
    }
    __syncthreads();

    int w = w0 + threadIdx.x, h = h0 + threadIdx.y;
    int p = h*MSZ + w;

    float gx = ((float)w + 0.5f)*2.0f/480.0f - 1.0f;
    float gy = ((float)h + 0.5f)*2.0f/480.0f - 1.0f;
    float x = (gx + sx + 1.0f)*0.5f*479.0f;
    float y = (gy + sy + 1.0f)*0.5f*479.0f;
    float x0f = floorf(x), y0f = floorf(y);
    int x0 = (int)x0f, y0 = (int)y0f;
    float wx = x - x0f, wy = y - y0f;
    float w00 = (1.f-wx)*(1.f-wy), w10 = wx*(1.f-wy);
    float w01 = (1.f-wx)*wy,       w11 = wx*wy;

    float res[AVC];
    #pragma unroll
    for (int ch = 0; ch < AVC; ++ch) {
        res[ch] = w00*rot_fetch(b,ch,x0,  y0  )
                + w10*rot_fetch(b,ch,x0+1,y0  )
                + w01*rot_fetch(b,ch,x0,  y0+1)
                + w11*rot_fetch(b,ch,x0+1,y0+1);
    }

    float* to = translated + (size_t)b*CC*NPIX + p;
    to[0]              = res[0];
    to[(size_t)NPIX]   = res[1];
    to[(size_t)2*NPIX] = 0.f;
    to[(size_t)3*NPIX] = 0.f;
    #pragma unroll
    for (int k = 0; k < 16; ++k)
        to[(size_t)(4+k)*NPIX] = res[2+k];

    int ty = threadIdx.y, tx = threadIdx.x;
    float mp = -INFINITY;
    #pragma unroll
    for (int dy = 0; dy < 3; ++dy)
        #pragma unroll
        for (int dx = 0; dx < 3; ++dx)
            mp = fmaxf(mp, s0[ty+dy][tx+dx]);

    float t1v = res[1];
    bool eve0 = (eve_angle[b] == 0.0f);
    bool kill = ((t1v - mp) > 0.8f) && eve0;

    float ts0 = res[18];
    float ts1 = t1v;
    if (b == 0) {
        float sm = 0.f;
        int ys0 = g_sc[1] - 30, xs0 = g_sc[0] - 30;
        int ii = h - ys0, jj = w - xs0;
        if (ii >= 0 && ii < 60 && jj >= 0 && jj < 60) {
            float di = (float)ii + 0.5f - 30.0f;
            float dj = (float)jj + 0.5f - 30.0f;
            if (di*di + dj*dj <= 900.0f) sm = 1.0f;
        }
        ts0 *= sm; ts1 *= sm;
    }
    bool kill_s = ((ts1 - ts0) > 0.8f) && eve0;

    const float* ml = maps_last + (size_t)b*CC*NPIX + p;
    float* mo = map_pred       + (size_t)b*CC*NPIX + p;
    float* so = map_pred_stair + (size_t)b*CC*NPIX + p;
    #pragma unroll
    for (int c = 0; c < CC; ++c) {
        float t  = (c == 0) ? res[0] : (c == 1) ? res[1]
                 : (c < 4)  ? 0.f    : res[c-2];
        float m  = ml[(size_t)c*NPIX];
        float mv = fmaxf(m, t);
        float ts = (c == 0) ? ts0 : (c == 1) ? ts1 : t;
        float sv = fmaxf(m, ts);
        if (c == 0) {
            if (kill)   mv = 0.f;
            if (kill_s) sv = 0.f;
        }
        mo[(size_t)c*NPIX] = mv;
        so[(size_t)c*NPIX] = sv;
    }
}

// ---------------- streams/events (created once, host-side) ----------------
struct HxStreams {
    cudaStream_t s[3];
    cudaEvent_t  fork;
    cudaEvent_t  done[3];
    HxStreams() {
        for (int i = 0; i < 3; ++i)
            cudaStreamCreateWithFlags(&s[i], cudaStreamNonBlocking);
        cudaEventCreateWithFlags(&fork, cudaEventDisableTiming);
        for (int i = 0; i < 3; ++i)
            cudaEventCreateWithFlags(&done[i], cudaEventDisableTiming);
    }
};
static HxStreams g_hx;

// ---------------- launch: 4 per-batch chains, forked after k_pose ----------------
extern "C" void kernel_launch(void* const* d_in, const int* in_sizes, int n_in,
                              void* d_out, int out_size)
{
    const float* obs        = (const float*)d_in[0];
    const float* pose_obs   = (const float*)d_in[1];
    const float* maps_last  = (const float*)d_in[2];
    const float* poses_last = (const float*)d_in[3];
    const float* eve_angle  = (const float*)d_in[4];
    float* out = (float*)d_out;

    float* translated     = out;
    float* map_pred       = out + (size_t)BSZ*CC*NPIX;
    float* map_pred_stair = out + 2*(size_t)BSZ*CC*NPIX;
    float* out_poses      = out + 3*(size_t)BSZ*CC*NPIX;

    k_pose<<<1, 32>>>(pose_obs, poses_last, eve_angle, out_poses);
    cudaEventRecord(g_hx.fork, 0);
    for (int i = 0; i < 3; ++i)
        cudaStreamWaitEvent(g_hx.s[i], g_hx.fork, 0);

    dim3 tfgrid(MSZ/16, MSZ/16), tfblock(16, 16);
    for (int b = 0; b < BSZ; ++b) {
        cudaStream_t st = (b == 0) ? (cudaStream_t)0 : g_hx.s[b-1];
        k_splat <<<(HH*WW + 255)/256,     256, 0, st>>>(obs, b);
        k_reduce<<<(VRD*VRD*32 + 255)/256,256, 0, st>>>(b);
        k_rot   <<<(RSZ*RSZ + 255)/256,   256, 0, st>>>(b);
        k_tf    <<<tfgrid, tfblock, 0, st>>>(maps_last, eve_angle, translated,
                                             map_pred, map_pred_stair, b);
    }
    for (int i = 0; i < 3; ++i) {
        cudaEventRecord(g_hx.done[i], g_hx.s[i]);
        cudaStreamWaitEvent((cudaStream_t)0, g_hx.done[i], 0);
    }
}